// round 8
// baseline (speedup 1.0000x reference)
#include <cuda_runtime.h>
#include <math.h>

// Problem constants (from reference)
#define BB 256
#define GG 2048
#define FF 128
#define RR 512
#define KK 128          // top-k == F
#define NTHREADS 1024
#define TILE_ROWS 32
#define TILE_STRIDE 129 // padded row stride for conflict-free transposed reads

struct SmemT {
    unsigned long long key[GG];          // packed (sortable-float << 32) | (2047-idx)
    float h[RR];                         // h_t row
    float scorer[FF];                    // normalized scorer
    float tanhv[KK];                     // tanh of top-k vals
    float red[NTHREADS];                 // reduction scratch
    float tile[TILE_ROWS * TILE_STRIDE]; // gathered 32x128 chunk (padded)
};

// float -> order-preserving uint (ascending)
__device__ __forceinline__ unsigned int f2u(float f) {
    unsigned int b = __float_as_uint(f);
    return (b & 0x80000000u) ? ~b : (b | 0x80000000u);
}
__device__ __forceinline__ float u2f(unsigned int u) {
    unsigned int b = (u & 0x80000000u) ? (u & 0x7fffffffu) : ~u;
    return __uint_as_float(b);
}

__global__ void __launch_bounds__(NTHREADS, 2)
topk_fused_kernel(const float* __restrict__ emb,    // [B,G,F]
                  const float* __restrict__ mask,   // [B,G]
                  const float* __restrict__ h_t,    // [B,R]
                  const float* __restrict__ W,      // [R,F]
                  const float* __restrict__ bmap,   // [F]
                  float* __restrict__ out,          // [B,F,K]
                  float* __restrict__ pol)          // [B]
{
    extern __shared__ char raw[];
    SmemT* s = reinterpret_cast<SmemT*>(raw);

    const int tid  = threadIdx.x;
    const int b    = blockIdx.x;
    const int lane = tid & 31;
    const int w    = tid >> 5;

    const size_t emb_base = (size_t)b * GG * FF;

    // ---------------- 1. scorer = tanh(h_t[b] @ W + bmap), then / ||.|| ------
    if (tid < RR) s->h[tid] = h_t[(size_t)b * RR + tid];
    __syncthreads();

    {
        const int f  = tid & (FF - 1);
        const int gr = tid >> 7;          // 0..7, each covers 64 rows of R
        float part = 0.f;
        const int r0 = gr * 64;
        #pragma unroll 8
        for (int r = 0; r < 64; r++) {
            part += s->h[r0 + r] * W[(r0 + r) * FF + f];
        }
        s->red[tid] = part;
    }
    __syncthreads();

    if (tid < FF) {
        float acc = bmap[tid];
        #pragma unroll
        for (int gr = 0; gr < 8; gr++) acc += s->red[gr * FF + tid];
        float t = tanhf(acc);
        s->scorer[tid] = t;
        float sq = t * t;
        #pragma unroll
        for (int o = 16; o; o >>= 1) sq += __shfl_xor_sync(0xffffffffu, sq, o);
        if (lane == 0) s->red[w] = sq;   // warps 0..3
    }
    __syncthreads();
    if (tid == 0) {
        float n2 = s->red[0] + s->red[1] + s->red[2] + s->red[3];
        s->red[8] = 1.0f / sqrtf(n2);
    }
    __syncthreads();
    if (tid < FF) s->scorer[tid] *= s->red[8];
    __syncthreads();

    // ---------------- 2. scores[g] = emb[b,g,:] . scorer + mask --------------
    // quad-per-row: 4 lanes share a row (32 floats each), 8 rows per warp-pass,
    // 8 passes per warp. Only 2 shuffles per row, 8 independent LDG.128/lane.
    {
        const int q  = lane >> 2;     // row-in-pass 0..7
        const int lq = lane & 3;      // quad lane 0..3
        // scorer float4s this lane needs: cols lq*4 + i*16
        float4 scv[8];
        #pragma unroll
        for (int i = 0; i < 8; i++)
            scv[i] = *reinterpret_cast<const float4*>(&s->scorer[lq * 4 + i * 16]);

        #pragma unroll
        for (int p = 0; p < 8; p++) {
            const int g = w * 64 + p * 8 + q;
            const float4* rp = reinterpret_cast<const float4*>(emb + emb_base + (size_t)g * FF);
            float d = 0.f;
            #pragma unroll
            for (int i = 0; i < 8; i++) {
                float4 e = rp[lq + i * 4];
                d += e.x * scv[i].x + e.y * scv[i].y + e.z * scv[i].z + e.w * scv[i].w;
            }
            d += __shfl_xor_sync(0xffffffffu, d, 1);
            d += __shfl_xor_sync(0xffffffffu, d, 2);
            if (lq == 0) {
                float sv = d + mask[(size_t)b * GG + g];
                s->key[g] = ((unsigned long long)f2u(sv) << 32)
                          | (unsigned int)(GG - 1 - g);
            }
        }
    }
    __syncthreads();

    // ---------------- 3. bitonic sort, descending keys -----------------------
    // key = (sortable_value << 32) | (2047-idx): descending key order ==
    // descending value, ties -> ascending index (jax top_k semantics).
    // Steps with j<=32 touch only the 64-element segment owned by one warp ->
    // __syncwarp suffices.
    for (int k2 = 2; k2 <= GG; k2 <<= 1) {
        int j = k2 >> 1;
        for (; j >= 64; j >>= 1) {
            int i   = ((tid & ~(j - 1)) << 1) | (tid & (j - 1));
            int ixj = i | j;
            bool up = ((i & k2) == 0);
            unsigned long long a = s->key[i], c = s->key[ixj];
            if (up ? (a < c) : (a > c)) { s->key[i] = c; s->key[ixj] = a; }
            __syncthreads();
        }
        for (; j > 0; j >>= 1) {
            int i   = ((tid & ~(j - 1)) << 1) | (tid & (j - 1));
            int ixj = i | j;
            bool up = ((i & k2) == 0);
            unsigned long long a = s->key[i], c = s->key[ixj];
            if (up ? (a < c) : (a > c)) { s->key[i] = c; s->key[ixj] = a; }
            __syncwarp();
        }
        __syncthreads();
    }

    // ---------------- 4. log-softmax denom + policy score + tanh(topk) -------
    const float vmax = u2f((unsigned int)(s->key[0] >> 32));
    {
        float v1 = u2f((unsigned int)(s->key[tid] >> 32));
        float v2 = u2f((unsigned int)(s->key[tid + NTHREADS] >> 32));
        float le = __expf(v1 - vmax) + __expf(v2 - vmax);
        #pragma unroll
        for (int o = 16; o; o >>= 1) le += __shfl_xor_sync(0xffffffffu, le, o);
        if (lane == 0) s->red[w] = le;             // slots 0..31
    }
    if (tid < KK) {
        float v = u2f((unsigned int)(s->key[tid] >> 32));
        s->tanhv[tid] = tanhf(v);
        float tp = v;
        #pragma unroll
        for (int o = 16; o; o >>= 1) tp += __shfl_xor_sync(0xffffffffu, tp, o);
        if (lane == 0) s->red[32 + w] = tp;        // slots 32..35 (warps 0..3)
    }
    __syncthreads();
    if (tid == 0) {
        float ssum = 0.f;
        #pragma unroll
        for (int i = 0; i < 32; i++) ssum += s->red[i];
        float topsum = s->red[32] + s->red[33] + s->red[34] + s->red[35];
        pol[b] = topsum * (1.0f / KK) - vmax - __logf(ssum);
    }

    // ---------------- 5/6. chunked gather (32 rows) + transposed write -------
    #pragma unroll 1
    for (int c = 0; c < KK / TILE_ROWS; c++) {
        // gather: warp w loads selected row #(c*32+w), fully coalesced.
        // NOTE: scalar smem stores — &tile[w*129 + lane*4] is NOT 16B-aligned
        // for odd w (129*4 = 516 bytes), so an STS.128 here traps.
        {
            const int k   = c * TILE_ROWS + w;
            const int row = GG - 1 - (int)(unsigned int)(s->key[k] & 0xffffffffu);
            float4 e = *reinterpret_cast<const float4*>(
                emb + emb_base + (size_t)row * FF + lane * 4);
            float* tp2 = &s->tile[w * TILE_STRIDE + lane * 4];
            tp2[0] = e.x; tp2[1] = e.y; tp2[2] = e.z; tp2[3] = e.w;
        }
        __syncthreads();
        // write out[b, f, c*32 + kl] = tile[kl][f] * tanhv, k-contiguous stores
        {
            const int kl = tid & 31;
            const int f0 = tid >> 5;     // 0..31
            const float tv = s->tanhv[c * TILE_ROWS + kl];
            float* ob = out + (size_t)b * FF * KK + c * TILE_ROWS;
            #pragma unroll
            for (int f = f0; f < FF; f += 32)
                ob[(size_t)f * KK + kl] = s->tile[kl * TILE_STRIDE + f] * tv;
        }
        __syncthreads();
    }
}

extern "C" void kernel_launch(void* const* d_in, const int* in_sizes, int n_in,
                              void* d_out, int out_size) {
    const float* emb  = (const float*)d_in[0]; // node_embs [B,G,F]
    const float* mask = (const float*)d_in[1]; // [B,G]
    const float* h_t  = (const float*)d_in[2]; // [B,R]
    const float* W    = (const float*)d_in[3]; // [R,F]
    const float* bmap = (const float*)d_in[4]; // [F]

    float* out = (float*)d_out;                 // [B,F,K] then [B]
    float* pol = out + (size_t)BB * FF * KK;

    const size_t smem = sizeof(SmemT);
    cudaFuncSetAttribute(topk_fused_kernel,
                         cudaFuncAttributeMaxDynamicSharedMemorySize, (int)smem);

    topk_fused_kernel<<<BB, NTHREADS, smem>>>(emb, mask, h_t, W, bmap, out, pol);
}

// round 9
// speedup vs baseline: 1.2516x; 1.2516x over previous
#include <cuda_runtime.h>
#include <math.h>

// Problem constants (from reference)
#define BB 256
#define GG 2048
#define FF 128
#define RR 512
#define KK 128          // top-k == F
#define TILE_ROWS 32
#define TILE_STRIDE 129

// Scratch (static device memory — no allocation)
__device__ float g_scorer[BB * FF];   // normalized scorer per batch
__device__ float g_scores[BB * GG];   // scores (incl. mask)

// float -> order-preserving uint (ascending)
__device__ __forceinline__ unsigned int f2u(float f) {
    unsigned int b = __float_as_uint(f);
    return (b & 0x80000000u) ? ~b : (b | 0x80000000u);
}
__device__ __forceinline__ float u2f(unsigned int u) {
    unsigned int b = (u & 0x80000000u) ? (u & 0x7fffffffu) : ~u;
    return __uint_as_float(b);
}

// ========================= Kernel A0: scorer ================================
// grid 256, 1024 threads. scorer[b] = tanh(h_t[b] @ W + bmap) / ||.||
__global__ void __launch_bounds__(1024)
scorer_kernel(const float* __restrict__ h_t,   // [B,R]
              const float* __restrict__ W,     // [R,F]
              const float* __restrict__ bmap)  // [F]
{
    __shared__ float h[RR];
    __shared__ float red[1024];
    const int tid = threadIdx.x;
    const int b   = blockIdx.x;
    const int lane = tid & 31;
    const int w    = tid >> 5;

    if (tid < RR) h[tid] = h_t[(size_t)b * RR + tid];
    __syncthreads();

    {
        const int f  = tid & (FF - 1);
        const int gr = tid >> 7;          // 0..7, each covers 64 rows of R
        float part = 0.f;
        const int r0 = gr * 64;
        #pragma unroll 8
        for (int r = 0; r < 64; r++)
            part += h[r0 + r] * W[(r0 + r) * FF + f];
        red[tid] = part;
    }
    __syncthreads();

    __shared__ float sc[FF];
    if (tid < FF) {
        float acc = bmap[tid];
        #pragma unroll
        for (int gr = 0; gr < 8; gr++) acc += red[gr * FF + tid];
        float t = tanhf(acc);
        sc[tid] = t;
        float sq = t * t;
        #pragma unroll
        for (int o = 16; o; o >>= 1) sq += __shfl_xor_sync(0xffffffffu, sq, o);
        if (lane == 0) red[w] = sq;   // warps 0..3
    }
    __syncthreads();
    if (tid == 0) red[8] = rsqrtf(red[0] + red[1] + red[2] + red[3]);
    __syncthreads();
    if (tid < FF) g_scorer[b * FF + tid] = sc[tid] * red[8];
}

// ========================= Kernel A: scores =================================
// grid 2048 (= 256 b x 8 slabs), 256 threads. Pure streaming.
__global__ void __launch_bounds__(256)
score_kernel(const float* __restrict__ emb,   // [B,G,F]
             const float* __restrict__ mask)  // [B,G]
{
    __shared__ float sc[FF];
    const int tid  = threadIdx.x;
    const int cta  = blockIdx.x;
    const int b    = cta >> 3;
    const int slab = cta & 7;
    const int lane = tid & 31;
    const int w    = tid >> 5;

    if (tid < FF) sc[tid] = g_scorer[b * FF + tid];
    __syncthreads();

    const size_t emb_base = (size_t)b * GG * FF;
    const int q  = lane >> 2;     // row-in-pass 0..7
    const int lq = lane & 3;      // quad lane 0..3

    float4 scv[8];
    #pragma unroll
    for (int i = 0; i < 8; i++)
        scv[i] = *reinterpret_cast<const float4*>(&sc[lq * 4 + i * 16]);

    const int g_base = slab * 256 + w * 32;
    #pragma unroll
    for (int p = 0; p < 4; p++) {
        const int g = g_base + p * 8 + q;
        const float4* rp = reinterpret_cast<const float4*>(emb + emb_base + (size_t)g * FF);
        float d = 0.f;
        #pragma unroll
        for (int i = 0; i < 8; i++) {
            float4 e = rp[lq + i * 4];
            d += e.x * scv[i].x + e.y * scv[i].y + e.z * scv[i].z + e.w * scv[i].w;
        }
        d += __shfl_xor_sync(0xffffffffu, d, 1);
        d += __shfl_xor_sync(0xffffffffu, d, 2);
        if (lq == 0)
            g_scores[(size_t)b * GG + g] = d + mask[(size_t)b * GG + g];
    }
}

// ========================= Kernel B: sort + epilogue ========================
// grid 256, 1024 threads, ~33 KB static smem -> 2 CTAs/SM.
__global__ void __launch_bounds__(1024, 2)
topk_kernel(const float* __restrict__ emb,    // [B,G,F]
            float* __restrict__ out,          // [B,F,K]
            float* __restrict__ pol)          // [B]
{
    __shared__ unsigned long long key[GG];
    __shared__ float tanhv[KK];
    __shared__ float red[64];
    __shared__ float tile[TILE_ROWS * TILE_STRIDE];

    const int tid  = threadIdx.x;
    const int b    = blockIdx.x;
    const int lane = tid & 31;
    const int w    = tid >> 5;
    const size_t emb_base = (size_t)b * GG * FF;

    // load scores -> packed keys: (sortable_val << 32) | (2047 - idx)
    {
        const float* sp = g_scores + (size_t)b * GG;
        float v0 = sp[tid];
        float v1 = sp[tid + 1024];
        key[tid]        = ((unsigned long long)f2u(v0) << 32) | (unsigned int)(GG - 1 - tid);
        key[tid + 1024] = ((unsigned long long)f2u(v1) << 32) | (unsigned int)(GG - 1 - (tid + 1024));
    }
    __syncthreads();

    // bitonic sort, descending keys; j<=32 steps are warp-local
    for (int k2 = 2; k2 <= GG; k2 <<= 1) {
        int j = k2 >> 1;
        for (; j >= 64; j >>= 1) {
            int i   = ((tid & ~(j - 1)) << 1) | (tid & (j - 1));
            int ixj = i | j;
            bool up = ((i & k2) == 0);
            unsigned long long a = key[i], c = key[ixj];
            if (up ? (a < c) : (a > c)) { key[i] = c; key[ixj] = a; }
            __syncthreads();
        }
        for (; j > 0; j >>= 1) {
            int i   = ((tid & ~(j - 1)) << 1) | (tid & (j - 1));
            int ixj = i | j;
            bool up = ((i & k2) == 0);
            unsigned long long a = key[i], c = key[ixj];
            if (up ? (a < c) : (a > c)) { key[i] = c; key[ixj] = a; }
            __syncwarp();
        }
        __syncthreads();
    }

    // log-softmax denom + policy + tanh(topk)
    const float vmax = u2f((unsigned int)(key[0] >> 32));
    {
        float v1 = u2f((unsigned int)(key[tid] >> 32));
        float v2 = u2f((unsigned int)(key[tid + 1024] >> 32));
        float le = __expf(v1 - vmax) + __expf(v2 - vmax);
        #pragma unroll
        for (int o = 16; o; o >>= 1) le += __shfl_xor_sync(0xffffffffu, le, o);
        if (lane == 0) red[w] = le;             // slots 0..31
    }
    if (tid < KK) {
        float v = u2f((unsigned int)(key[tid] >> 32));
        tanhv[tid] = tanhf(v);
        float tp = v;
        #pragma unroll
        for (int o = 16; o; o >>= 1) tp += __shfl_xor_sync(0xffffffffu, tp, o);
        if (lane == 0) red[32 + w] = tp;        // slots 32..35
    }
    __syncthreads();
    if (tid == 0) {
        float ssum = 0.f;
        #pragma unroll
        for (int i = 0; i < 32; i++) ssum += red[i];
        float topsum = red[32] + red[33] + red[34] + red[35];
        pol[b] = topsum * (1.0f / KK) - vmax - __logf(ssum);
    }

    // chunked gather (32 rows) + transposed, scaled write
    #pragma unroll 1
    for (int c = 0; c < KK / TILE_ROWS; c++) {
        {
            const int k   = c * TILE_ROWS + w;
            const int row = GG - 1 - (int)(unsigned int)(key[k] & 0xffffffffu);
            float4 e = *reinterpret_cast<const float4*>(
                emb + emb_base + (size_t)row * FF + lane * 4);
            // scalar stores: &tile[w*129 + lane*4] is not 16B aligned for odd w
            float* tp2 = &tile[w * TILE_STRIDE + lane * 4];
            tp2[0] = e.x; tp2[1] = e.y; tp2[2] = e.z; tp2[3] = e.w;
        }
        __syncthreads();
        {
            const int kl = tid & 31;
            const int f0 = tid >> 5;     // 0..31
            const float tv = tanhv[c * TILE_ROWS + kl];
            float* ob = out + (size_t)b * FF * KK + c * TILE_ROWS;
            #pragma unroll
            for (int f = f0; f < FF; f += 32)
                ob[(size_t)f * KK + kl] = tile[kl * TILE_STRIDE + f] * tv;
        }
        __syncthreads();
    }
}

extern "C" void kernel_launch(void* const* d_in, const int* in_sizes, int n_in,
                              void* d_out, int out_size) {
    const float* emb  = (const float*)d_in[0]; // node_embs [B,G,F]
    const float* mask = (const float*)d_in[1]; // [B,G]
    const float* h_t  = (const float*)d_in[2]; // [B,R]
    const float* W    = (const float*)d_in[3]; // [R,F]
    const float* bmap = (const float*)d_in[4]; // [F]

    float* out = (float*)d_out;                 // [B,F,K] then [B]
    float* pol = out + (size_t)BB * FF * KK;

    scorer_kernel<<<BB, 1024>>>(h_t, W, bmap);
    score_kernel<<<BB * 8, 256>>>(emb, mask);
    topk_kernel<<<BB, 1024>>>(emb, out, pol);
}

// round 13
// speedup vs baseline: 1.5086x; 1.2054x over previous
#include <cuda_runtime.h>
#include <math.h>

// Problem constants (from reference)
#define BB 256
#define GG 2048
#define FF 128
#define RR 512
#define KK 128          // top-k == F
#define TILE_ROWS 32
#define TILE_STRIDE 129
#define HBINS 4096

// Scratch (static device memory — no allocation)
__device__ float g_scorer[BB * FF];   // normalized scorer per batch
__device__ float g_scores[BB * GG];   // scores (incl. mask)

// float -> order-preserving uint (ascending)
__device__ __forceinline__ unsigned int f2u(float f) {
    unsigned int b = __float_as_uint(f);
    return (b & 0x80000000u) ? ~b : (b | 0x80000000u);
}
__device__ __forceinline__ float u2f(unsigned int u) {
    unsigned int b = (u & 0x80000000u) ? (u & 0x7fffffffu) : ~u;
    return __uint_as_float(b);
}

// ========================= Kernel A0: scorer (batch-4) ======================
// grid 64, 1024 threads. Each CTA: 4 batches, W loads reused 4x.
__global__ void __launch_bounds__(1024)
scorer_kernel(const float* __restrict__ h_t,   // [B,R]
              const float* __restrict__ W,     // [R,F]
              const float* __restrict__ bmap)  // [F]
{
    __shared__ float h4[4][RR];       // 8 KB
    __shared__ float red4[4][1024];   // 16 KB
    __shared__ float nred[16];
    __shared__ float inv4[4];

    const int tid = threadIdx.x;
    const int b0  = blockIdx.x * 4;
    const int lane = tid & 31;

    for (int i = tid; i < 4 * RR; i += 1024)
        h4[i >> 9][i & (RR - 1)] = h_t[(size_t)b0 * RR + i];
    __syncthreads();

    {
        const int f  = tid & (FF - 1);
        const int gr = tid >> 7;          // 0..7, each covers 64 rows of R
        const int r0 = gr * 64;
        float p0 = 0.f, p1 = 0.f, p2 = 0.f, p3 = 0.f;
        #pragma unroll 8
        for (int r = 0; r < 64; r++) {
            float wv = W[(r0 + r) * FF + f];
            p0 += h4[0][r0 + r] * wv;
            p1 += h4[1][r0 + r] * wv;
            p2 += h4[2][r0 + r] * wv;
            p3 += h4[3][r0 + r] * wv;
        }
        red4[0][tid] = p0; red4[1][tid] = p1;
        red4[2][tid] = p2; red4[3][tid] = p3;
    }
    __syncthreads();

    float tval = 0.f;
    const int bb = tid >> 7;   // valid for tid < 512
    const int ff = tid & (FF - 1);
    if (tid < 512) {
        float acc = bmap[ff];
        #pragma unroll
        for (int gr = 0; gr < 8; gr++) acc += red4[bb][gr * FF + ff];
        tval = tanhf(acc);
        float sq = tval * tval;
        #pragma unroll
        for (int o = 16; o; o >>= 1) sq += __shfl_xor_sync(0xffffffffu, sq, o);
        if (lane == 0) nred[tid >> 5] = sq;   // warps 0..15
    }
    __syncthreads();
    if (tid < 4)
        inv4[tid] = rsqrtf(nred[4*tid] + nred[4*tid+1] + nred[4*tid+2] + nred[4*tid+3]);
    __syncthreads();
    if (tid < 512)
        g_scorer[(size_t)(b0 + bb) * FF + ff] = tval * inv4[bb];
}

// ========================= Kernel A: scores =================================
// grid 2048 (= 256 b x 8 slabs), 256 threads. Pure streaming.
__global__ void __launch_bounds__(256)
score_kernel(const float* __restrict__ emb,   // [B,G,F]
             const float* __restrict__ mask)  // [B,G]
{
    __shared__ float sc[FF];
    const int tid  = threadIdx.x;
    const int cta  = blockIdx.x;
    const int b    = cta >> 3;
    const int slab = cta & 7;
    const int lane = tid & 31;
    const int w    = tid >> 5;

    if (tid < FF) sc[tid] = g_scorer[b * FF + tid];
    __syncthreads();

    const size_t emb_base = (size_t)b * GG * FF;
    const int q  = lane >> 2;     // row-in-pass 0..7
    const int lq = lane & 3;      // quad lane 0..3

    float4 scv[8];
    #pragma unroll
    for (int i = 0; i < 8; i++)
        scv[i] = *reinterpret_cast<const float4*>(&sc[lq * 4 + i * 16]);

    const int g_base = slab * 256 + w * 32;
    #pragma unroll
    for (int p = 0; p < 4; p++) {
        const int g = g_base + p * 8 + q;
        const float4* rp = reinterpret_cast<const float4*>(emb + emb_base + (size_t)g * FF);
        float d = 0.f;
        #pragma unroll
        for (int i = 0; i < 8; i++) {
            float4 e = rp[lq + i * 4];
            d += e.x * scv[i].x + e.y * scv[i].y + e.z * scv[i].z + e.w * scv[i].w;
        }
        d += __shfl_xor_sync(0xffffffffu, d, 1);
        d += __shfl_xor_sync(0xffffffffu, d, 2);
        if (lq == 0)
            g_scores[(size_t)b * GG + g] = d + mask[(size_t)b * GG + g];
    }
}

// ========================= Kernel B: select + sort + epilogue ===============
// grid 256, 1024 threads, ~47 KB static smem.
__global__ void __launch_bounds__(1024, 2)
topk_kernel(const float* __restrict__ emb,    // [B,G,F]
            float* __restrict__ out,          // [B,F,K]
            float* __restrict__ pol)          // [B]
{
    __shared__ unsigned long long histspace[HBINS / 2];   // 16 KB (hist / fallback keys)
    __shared__ unsigned long long cand[256];              // 2 KB
    __shared__ unsigned int keys[GG];                     // 8 KB
    __shared__ int scan_s[1024];                          // 4 KB
    __shared__ float tile[TILE_ROWS * TILE_STRIDE];       // 16.5 KB
    __shared__ float tanhv[KK];
    __shared__ float redf[32];
    __shared__ float s_vmax, s_ssum;
    __shared__ int sB, sCntA, sB2, sCandTotal, sCandCnt;

    unsigned int* hist = (unsigned int*)histspace;

    const int tid  = threadIdx.x;
    const int b    = blockIdx.x;
    const int lane = tid & 31;
    const int w    = tid >> 5;
    const size_t emb_base = (size_t)b * GG * FF;

    // ---- load scores, compute keys ----
    const float* sp = g_scores + (size_t)b * GG;
    float v0 = sp[tid];
    float v1 = sp[tid + 1024];
    unsigned int u0 = f2u(v0), u1 = f2u(v1);
    keys[tid] = u0;
    keys[tid + 1024] = u1;

    // ---- block max ----
    {
        float m = fmaxf(v0, v1);
        #pragma unroll
        for (int o = 16; o; o >>= 1) m = fmaxf(m, __shfl_xor_sync(0xffffffffu, m, o));
        if (lane == 0) redf[w] = m;
    }
    __syncthreads();
    if (w == 0) {
        float m = redf[lane];
        #pragma unroll
        for (int o = 16; o; o >>= 1) m = fmaxf(m, __shfl_xor_sync(0xffffffffu, m, o));
        if (lane == 0) s_vmax = m;
    }
    __syncthreads();
    const float vmax = s_vmax;

    // ---- block expsum ----
    {
        float le = __expf(v0 - vmax) + __expf(v1 - vmax);
        #pragma unroll
        for (int o = 16; o; o >>= 1) le += __shfl_xor_sync(0xffffffffu, le, o);
        if (lane == 0) redf[w] = le;
    }
    __syncthreads();
    if (w == 0) {
        float sm = redf[lane];
        #pragma unroll
        for (int o = 16; o; o >>= 1) sm += __shfl_xor_sync(0xffffffffu, sm, o);
        if (lane == 0) s_ssum = sm;
    }

    // ---- level-1 histogram: bins = key >> 20 ----
    hist[tid] = 0; hist[tid + 1024] = 0; hist[tid + 2048] = 0; hist[tid + 3072] = 0;
    __syncthreads();
    atomicAdd(&hist[u0 >> 20], 1u);
    atomicAdd(&hist[u1 >> 20], 1u);
    __syncthreads();

    // suffix scan over per-thread (4-bin) sums
    {
        int s = (int)(hist[4*tid] + hist[4*tid+1] + hist[4*tid+2] + hist[4*tid+3]);
        scan_s[tid] = s;
    }
    __syncthreads();
    for (int off = 1; off < 1024; off <<= 1) {
        int v = (tid + off < 1024) ? scan_s[tid + off] : 0;
        __syncthreads();
        scan_s[tid] += v;
        __syncthreads();
    }
    {
        int Sown  = scan_s[tid];
        int Snext = (tid < 1023) ? scan_s[tid + 1] : 0;
        if (Sown >= KK && Snext < KK) {
            int c = Snext;
            for (int bin = 4 * tid + 3; bin >= 4 * tid; bin--) {
                int h = (int)hist[bin];
                if (c + h >= KK) { sB = bin; sCntA = c; break; }
                c += h;
            }
        }
    }
    __syncthreads();
    const int B = sB;
    const int cntA = sCntA;
    const int needed = KK - cntA;

    // ---- level-2 histogram among bin-B elements: bins = (key>>8)&0xFFF ----
    hist[tid] = 0; hist[tid + 1024] = 0; hist[tid + 2048] = 0; hist[tid + 3072] = 0;
    if (tid < 256) cand[tid] = 0ull;
    if (tid == 0) sCandCnt = 0;
    __syncthreads();
    if ((int)(u0 >> 20) == B) atomicAdd(&hist[(u0 >> 8) & 0xFFFu], 1u);
    if ((int)(u1 >> 20) == B) atomicAdd(&hist[(u1 >> 8) & 0xFFFu], 1u);
    __syncthreads();
    {
        int s = (int)(hist[4*tid] + hist[4*tid+1] + hist[4*tid+2] + hist[4*tid+3]);
        scan_s[tid] = s;
    }
    __syncthreads();
    for (int off = 1; off < 1024; off <<= 1) {
        int v = (tid + off < 1024) ? scan_s[tid + off] : 0;
        __syncthreads();
        scan_s[tid] += v;
        __syncthreads();
    }
    {
        int Sown  = scan_s[tid];
        int Snext = (tid < 1023) ? scan_s[tid + 1] : 0;
        if (Sown >= needed && Snext < needed) {
            int c = Snext;
            for (int bin = 4 * tid + 3; bin >= 4 * tid; bin--) {
                int h = (int)hist[bin];
                if (c + h >= needed) {
                    sB2 = bin;
                    sCandTotal = cntA + c + h;
                    break;
                }
                c += h;
            }
        }
    }
    __syncthreads();
    const int B2 = sB2;
    const int candTotal = sCandTotal;
    const unsigned int thrkey = ((unsigned int)B << 20) | ((unsigned int)B2 << 8);

    if (candTotal <= 256) {
        // ---- compact candidates ----
        if (u0 >= thrkey) {
            int p = atomicAdd(&sCandCnt, 1);
            cand[p] = ((unsigned long long)u0 << 32) | (unsigned int)(GG - 1 - tid);
        }
        if (u1 >= thrkey) {
            int p = atomicAdd(&sCandCnt, 1);
            cand[p] = ((unsigned long long)u1 << 32) | (unsigned int)(GG - 1 - (tid + 1024));
        }
        __syncthreads();
        // ---- bitonic sort 256 candidates, descending ----
        for (int k2 = 2; k2 <= 256; k2 <<= 1) {
            for (int j = k2 >> 1; j > 0; j >>= 1) {
                if (tid < 128) {
                    int i   = ((tid & ~(j - 1)) << 1) | (tid & (j - 1));
                    int ixj = i | j;
                    bool up = ((i & k2) == 0);
                    unsigned long long a = cand[i], c = cand[ixj];
                    if (up ? (a < c) : (a > c)) { cand[i] = c; cand[ixj] = a; }
                }
                __syncthreads();
            }
        }
    } else {
        // ---- fallback (ties overflow): full bitonic sort of 2048 ----
        unsigned long long* fullkey = histspace;
        fullkey[tid]        = ((unsigned long long)u0 << 32) | (unsigned int)(GG - 1 - tid);
        fullkey[tid + 1024] = ((unsigned long long)u1 << 32) | (unsigned int)(GG - 1 - (tid + 1024));
        __syncthreads();
        for (int k2 = 2; k2 <= GG; k2 <<= 1) {
            for (int j = k2 >> 1; j > 0; j >>= 1) {
                int i   = ((tid & ~(j - 1)) << 1) | (tid & (j - 1));
                int ixj = i | j;
                bool up = ((i & k2) == 0);
                unsigned long long a = fullkey[i], c = fullkey[ixj];
                if (up ? (a < c) : (a > c)) { fullkey[i] = c; fullkey[ixj] = a; }
                __syncthreads();
            }
        }
        if (tid < 128) cand[tid] = fullkey[tid];
        __syncthreads();
    }

    // ---- tanh(topk) + policy score ----
    if (tid < KK) {
        float v = u2f((unsigned int)(cand[tid] >> 32));
        tanhv[tid] = tanhf(v);
        float tp = v;
        #pragma unroll
        for (int o = 16; o; o >>= 1) tp += __shfl_xor_sync(0xffffffffu, tp, o);
        if (lane == 0) redf[w] = tp;   // warps 0..3
    }
    __syncthreads();
    if (tid == 0) {
        float topsum = redf[0] + redf[1] + redf[2] + redf[3];
        pol[b] = topsum * (1.0f / KK) - vmax - __logf(s_ssum);
    }

    // ---- chunked gather (32 rows) + transposed, scaled write ----
    #pragma unroll 1
    for (int c = 0; c < KK / TILE_ROWS; c++) {
        {
            const int k   = c * TILE_ROWS + w;
            const int row = GG - 1 - (int)(unsigned int)(cand[k] & 0xffffffffu);
            float4 e = *reinterpret_cast<const float4*>(
                emb + emb_base + (size_t)row * FF + lane * 4);
            // scalar stores: &tile[w*129 + lane*4] not 16B-aligned for odd w
            float* tp2 = &tile[w * TILE_STRIDE + lane * 4];
            tp2[0] = e.x; tp2[1] = e.y; tp2[2] = e.z; tp2[3] = e.w;
        }
        __syncthreads();
        {
            const int kl = tid & 31;
            const int f0 = tid >> 5;     // 0..31
            const float tv = tanhv[c * TILE_ROWS + kl];
            float* ob = out + (size_t)b * FF * KK + c * TILE_ROWS;
            #pragma unroll
            for (int f = f0; f < FF; f += 32)
                ob[(size_t)f * KK + kl] = tile[kl * TILE_STRIDE + f] * tv;
        }
        __syncthreads();
    }
}

extern "C" void kernel_launch(void* const* d_in, const int* in_sizes, int n_in,
                              void* d_out, int out_size) {
    const float* emb  = (const float*)d_in[0]; // node_embs [B,G,F]
    const float* mask = (const float*)d_in[1]; // [B,G]
    const float* h_t  = (const float*)d_in[2]; // [B,R]
    const float* W    = (const float*)d_in[3]; // [R,F]
    const float* bmap = (const float*)d_in[4]; // [F]

    float* out = (float*)d_out;                 // [B,F,K] then [B]
    float* pol = out + (size_t)BB * FF * KK;

    scorer_kernel<<<BB / 4, 1024>>>(h_t, W, bmap);
    score_kernel<<<BB * 8, 256>>>(emb, mask);
    topk_kernel<<<BB, 1024>>>(emb, out, pol);
}

// round 14
// speedup vs baseline: 1.5635x; 1.0364x over previous
#include <cuda_runtime.h>
#include <math.h>

// Problem constants (from reference)
#define BB 256
#define GG 2048
#define FF 128
#define RR 512
#define KK 128          // top-k == F
#define TILE_ROWS 32
#define TILE_STRIDE 129
#define HBINS 4096

// Scratch (static device memory — no allocation)
__device__ float g_part[BB * 4 * FF];  // split-K partial sums of h@W
__device__ float g_scores[BB * GG];    // scores (incl. mask)

// float -> order-preserving uint (ascending)
__device__ __forceinline__ unsigned int f2u(float f) {
    unsigned int b = __float_as_uint(f);
    return (b & 0x80000000u) ? ~b : (b | 0x80000000u);
}
__device__ __forceinline__ float u2f(unsigned int u) {
    unsigned int b = (u & 0x80000000u) ? (u & 0x7fffffffu) : ~u;
    return __uint_as_float(b);
}

// warp-level inclusive suffix scan (sum of lanes >= lane)
__device__ __forceinline__ int warp_suffix_incl(int v, int lane) {
    #pragma unroll
    for (int off = 1; off < 32; off <<= 1) {
        int t = __shfl_down_sync(0xffffffffu, v, off);
        if (lane + off < 32) v += t;
    }
    return v;
}

// ================= Kernel 1: scorer split-K partials ========================
// grid 256 = 64 batch-groups x 4 K-slices, 256 threads.
// g_part[b][ks][f] = sum_{r in slice ks} h_t[b][r] * W[r][f]
__global__ void __launch_bounds__(256)
scorer_partial_kernel(const float* __restrict__ h_t,   // [B,R]
                      const float* __restrict__ W)     // [R,F]
{
    __shared__ float hs[4][128];     // h slice for 4 batches
    __shared__ float part[4][FF];    // sub-slice combine

    const int tid = threadIdx.x;
    const int bg  = blockIdx.x >> 2;       // batch group 0..63
    const int ks  = blockIdx.x & 3;        // K slice 0..3
    const int b0  = bg * 4;
    const int f   = tid & (FF - 1);
    const int sub = tid >> 7;              // 0/1: rows 0..63 / 64..127 of slice

    for (int i = tid; i < 4 * 128; i += 256) {
        int bidx = i >> 7, rl = i & 127;
        hs[bidx][rl] = h_t[(size_t)(b0 + bidx) * RR + ks * 128 + rl];
    }
    __syncthreads();

    const int rl0 = sub * 64;
    float p0 = 0.f, p1 = 0.f, p2 = 0.f, p3 = 0.f;
    #pragma unroll 8
    for (int r = 0; r < 64; r++) {
        float wv = W[(size_t)(ks * 128 + rl0 + r) * FF + f];
        p0 += hs[0][rl0 + r] * wv;
        p1 += hs[1][rl0 + r] * wv;
        p2 += hs[2][rl0 + r] * wv;
        p3 += hs[3][rl0 + r] * wv;
    }
    if (sub == 1) {
        part[0][f] = p0; part[1][f] = p1; part[2][f] = p2; part[3][f] = p3;
    }
    __syncthreads();
    if (sub == 0) {
        g_part[(size_t)(b0 + 0) * 512 + ks * 128 + f] = p0 + part[0][f];
        g_part[(size_t)(b0 + 1) * 512 + ks * 128 + f] = p1 + part[1][f];
        g_part[(size_t)(b0 + 2) * 512 + ks * 128 + f] = p2 + part[2][f];
        g_part[(size_t)(b0 + 3) * 512 + ks * 128 + f] = p3 + part[3][f];
    }
}

// ================= Kernel 2: scores (inline scorer finish) ==================
// grid 2048 (= 256 b x 8 slabs), 256 threads. Pure streaming after a tiny
// per-CTA scorer finish (sum partials + bias + tanh + normalize).
__global__ void __launch_bounds__(256)
score_kernel(const float* __restrict__ emb,   // [B,G,F]
             const float* __restrict__ mask,  // [B,G]
             const float* __restrict__ bmap)  // [F]
{
    __shared__ float sc[FF];
    __shared__ float nr[4];
    __shared__ float s_inv;

    const int tid  = threadIdx.x;
    const int cta  = blockIdx.x;
    const int b    = cta >> 3;
    const int slab = cta & 7;
    const int lane = tid & 31;

    if (tid < FF) {
        float acc = bmap[tid];
        #pragma unroll
        for (int ks = 0; ks < 4; ks++)
            acc += g_part[(size_t)b * 512 + ks * 128 + tid];
        float t = tanhf(acc);
        sc[tid] = t;
        float sq = t * t;
        #pragma unroll
        for (int o = 16; o; o >>= 1) sq += __shfl_xor_sync(0xffffffffu, sq, o);
        if (lane == 0) nr[tid >> 5] = sq;
    }
    __syncthreads();
    if (tid == 0) s_inv = rsqrtf(nr[0] + nr[1] + nr[2] + nr[3]);
    __syncthreads();
    const float inv = s_inv;

    const size_t emb_base = (size_t)b * GG * FF;
    const int w  = tid >> 5;
    const int q  = lane >> 2;     // row-in-pass 0..7
    const int lq = lane & 3;      // quad lane 0..3

    float4 scv[8];
    #pragma unroll
    for (int i = 0; i < 8; i++) {
        float4 v = *reinterpret_cast<const float4*>(&sc[lq * 4 + i * 16]);
        v.x *= inv; v.y *= inv; v.z *= inv; v.w *= inv;
        scv[i] = v;
    }

    const int g_base = slab * 256 + w * 32;
    #pragma unroll
    for (int p = 0; p < 4; p++) {
        const int g = g_base + p * 8 + q;
        const float4* rp = reinterpret_cast<const float4*>(emb + emb_base + (size_t)g * FF);
        float d = 0.f;
        #pragma unroll
        for (int i = 0; i < 8; i++) {
            float4 e = rp[lq + i * 4];
            d += e.x * scv[i].x + e.y * scv[i].y + e.z * scv[i].z + e.w * scv[i].w;
        }
        d += __shfl_xor_sync(0xffffffffu, d, 1);
        d += __shfl_xor_sync(0xffffffffu, d, 2);
        if (lq == 0)
            g_scores[(size_t)b * GG + g] = d + mask[(size_t)b * GG + g];
    }
}

// ================= Kernel 3: select + sort + epilogue =======================
// grid 256, 1024 threads.
__global__ void __launch_bounds__(1024, 2)
topk_kernel(const float* __restrict__ emb,    // [B,G,F]
            float* __restrict__ out,          // [B,F,K]
            float* __restrict__ pol)          // [B]
{
    __shared__ unsigned long long histspace[HBINS / 2];   // 16 KB (hist / fallback keys)
    __shared__ unsigned long long cand[256];              // 2 KB
    __shared__ float tile[TILE_ROWS * TILE_STRIDE];       // 16.5 KB
    __shared__ float tanhv[KK];
    __shared__ float redf[32];
    __shared__ int wsum[32];
    __shared__ float s_vmax, s_ssum;
    __shared__ int sB, sCntA, sB2, sCandTotal, sCandCnt;

    unsigned int* hist = (unsigned int*)histspace;

    const int tid  = threadIdx.x;
    const int b    = blockIdx.x;
    const int lane = tid & 31;
    const int w    = tid >> 5;
    const size_t emb_base = (size_t)b * GG * FF;

    // ---- load scores ----
    const float* sp = g_scores + (size_t)b * GG;
    float v0 = sp[tid];
    float v1 = sp[tid + 1024];
    unsigned int u0 = f2u(v0), u1 = f2u(v1);

    // ---- block max ----
    {
        float m = fmaxf(v0, v1);
        #pragma unroll
        for (int o = 16; o; o >>= 1) m = fmaxf(m, __shfl_xor_sync(0xffffffffu, m, o));
        if (lane == 0) redf[w] = m;
    }
    __syncthreads();
    if (w == 0) {
        float m = redf[lane];
        #pragma unroll
        for (int o = 16; o; o >>= 1) m = fmaxf(m, __shfl_xor_sync(0xffffffffu, m, o));
        if (lane == 0) s_vmax = m;
    }
    __syncthreads();
    const float vmax = s_vmax;

    // ---- block expsum ----
    {
        float le = __expf(v0 - vmax) + __expf(v1 - vmax);
        #pragma unroll
        for (int o = 16; o; o >>= 1) le += __shfl_xor_sync(0xffffffffu, le, o);
        if (lane == 0) redf[w] = le;
    }
    __syncthreads();
    if (w == 0) {
        float sm = redf[lane];
        #pragma unroll
        for (int o = 16; o; o >>= 1) sm += __shfl_xor_sync(0xffffffffu, sm, o);
        if (lane == 0) s_ssum = sm;
    }

    // ---- level-1 histogram: bins = key >> 20 ----
    hist[tid] = 0; hist[tid + 1024] = 0; hist[tid + 2048] = 0; hist[tid + 3072] = 0;
    __syncthreads();
    atomicAdd(&hist[u0 >> 20], 1u);
    atomicAdd(&hist[u1 >> 20], 1u);
    __syncthreads();

    // hierarchical suffix scan (2 barriers)
    {
        int s = (int)(hist[4*tid] + hist[4*tid+1] + hist[4*tid+2] + hist[4*tid+3]);
        int v = warp_suffix_incl(s, lane);
        if (lane == 0) wsum[w] = v;          // warp total
        __syncthreads();
        if (w == 0) {
            int t  = wsum[lane];
            int ts = warp_suffix_incl(t, lane);
            wsum[lane] = ts - t;             // sum of warps above
        }
        __syncthreads();
        int Sown  = v + wsum[w];
        int Snext = Sown - s;
        if (Sown >= KK && Snext < KK) {
            int c = Snext;
            for (int bin = 4 * tid + 3; bin >= 4 * tid; bin--) {
                int h = (int)hist[bin];
                if (c + h >= KK) { sB = bin; sCntA = c; break; }
                c += h;
            }
        }
    }
    __syncthreads();
    const int B = sB;
    const int cntA = sCntA;
    const int needed = KK - cntA;

    // ---- level-2 histogram among bin-B elements: bins = (key>>8)&0xFFF ----
    hist[tid] = 0; hist[tid + 1024] = 0; hist[tid + 2048] = 0; hist[tid + 3072] = 0;
    if (tid < 256) cand[tid] = 0ull;
    if (tid == 0) sCandCnt = 0;
    __syncthreads();
    if ((int)(u0 >> 20) == B) atomicAdd(&hist[(u0 >> 8) & 0xFFFu], 1u);
    if ((int)(u1 >> 20) == B) atomicAdd(&hist[(u1 >> 8) & 0xFFFu], 1u);
    __syncthreads();
    {
        int s = (int)(hist[4*tid] + hist[4*tid+1] + hist[4*tid+2] + hist[4*tid+3]);
        int v = warp_suffix_incl(s, lane);
        if (lane == 0) wsum[w] = v;
        __syncthreads();
        if (w == 0) {
            int t  = wsum[lane];
            int ts = warp_suffix_incl(t, lane);
            wsum[lane] = ts - t;
        }
        __syncthreads();
        int Sown  = v + wsum[w];
        int Snext = Sown - s;
        if (Sown >= needed && Snext < needed) {
            int c = Snext;
            for (int bin = 4 * tid + 3; bin >= 4 * tid; bin--) {
                int h = (int)hist[bin];
                if (c + h >= needed) {
                    sB2 = bin;
                    sCandTotal = cntA + c + h;
                    break;
                }
                c += h;
            }
        }
    }
    __syncthreads();
    const int B2 = sB2;
    const int candTotal = sCandTotal;
    const unsigned int thrkey = ((unsigned int)B << 20) | ((unsigned int)B2 << 8);

    if (candTotal <= 256) {
        // ---- compact candidates ----
        if (u0 >= thrkey) {
            int p = atomicAdd(&sCandCnt, 1);
            cand[p] = ((unsigned long long)u0 << 32) | (unsigned int)(GG - 1 - tid);
        }
        if (u1 >= thrkey) {
            int p = atomicAdd(&sCandCnt, 1);
            cand[p] = ((unsigned long long)u1 << 32) | (unsigned int)(GG - 1 - (tid + 1024));
        }
        __syncthreads();
        // ---- bitonic sort 256 candidates, descending ----
        for (int k2 = 2; k2 <= 256; k2 <<= 1) {
            for (int j = k2 >> 1; j > 0; j >>= 1) {
                if (tid < 128) {
                    int i   = ((tid & ~(j - 1)) << 1) | (tid & (j - 1));
                    int ixj = i | j;
                    bool up = ((i & k2) == 0);
                    unsigned long long a = cand[i], c = cand[ixj];
                    if (up ? (a < c) : (a > c)) { cand[i] = c; cand[ixj] = a; }
                }
                __syncthreads();
            }
        }
    } else {
        // ---- fallback (massive ties): full bitonic sort of 2048 ----
        unsigned long long* fullkey = histspace;
        fullkey[tid]        = ((unsigned long long)u0 << 32) | (unsigned int)(GG - 1 - tid);
        fullkey[tid + 1024] = ((unsigned long long)u1 << 32) | (unsigned int)(GG - 1 - (tid + 1024));
        __syncthreads();
        for (int k2 = 2; k2 <= GG; k2 <<= 1) {
            for (int j = k2 >> 1; j > 0; j >>= 1) {
                int i   = ((tid & ~(j - 1)) << 1) | (tid & (j - 1));
                int ixj = i | j;
                bool up = ((i & k2) == 0);
                unsigned long long a = fullkey[i], c = fullkey[ixj];
                if (up ? (a < c) : (a > c)) { fullkey[i] = c; fullkey[ixj] = a; }
                __syncthreads();
            }
        }
        if (tid < 128) cand[tid] = fullkey[tid];
        __syncthreads();
    }

    // ---- tanh(topk) + policy score ----
    if (tid < KK) {
        float v = u2f((unsigned int)(cand[tid] >> 32));
        tanhv[tid] = tanhf(v);
        float tp = v;
        #pragma unroll
        for (int o = 16; o; o >>= 1) tp += __shfl_xor_sync(0xffffffffu, tp, o);
        if (lane == 0) redf[w] = tp;   // warps 0..3
    }
    __syncthreads();
    if (tid == 0) {
        float topsum = redf[0] + redf[1] + redf[2] + redf[3];
        pol[b] = topsum * (1.0f / KK) - vmax - __logf(s_ssum);
    }

    // ---- chunked gather (32 rows) + transposed, scaled write ----
    #pragma unroll 1
    for (int c = 0; c < KK / TILE_ROWS; c++) {
        {
            const int k   = c * TILE_ROWS + w;
            const int row = GG - 1 - (int)(unsigned int)(cand[k] & 0xffffffffu);
            float4 e = *reinterpret_cast<const float4*>(
                emb + emb_base + (size_t)row * FF + lane * 4);
            // scalar stores: &tile[w*129 + lane*4] not 16B-aligned for odd w
            float* tp2 = &tile[w * TILE_STRIDE + lane * 4];
            tp2[0] = e.x; tp2[1] = e.y; tp2[2] = e.z; tp2[3] = e.w;
        }
        __syncthreads();
        {
            const int kl = tid & 31;
            const int f0 = tid >> 5;     // 0..31
            const float tv = tanhv[c * TILE_ROWS + kl];
            float* ob = out + (size_t)b * FF * KK + c * TILE_ROWS;
            #pragma unroll
            for (int f = f0; f < FF; f += 32)
                ob[(size_t)f * KK + kl] = tile[kl * TILE_STRIDE + f] * tv;
        }
        __syncthreads();
    }
}

extern "C" void kernel_launch(void* const* d_in, const int* in_sizes, int n_in,
                              void* d_out, int out_size) {
    const float* emb  = (const float*)d_in[0]; // node_embs [B,G,F]
    const float* mask = (const float*)d_in[1]; // [B,G]
    const float* h_t  = (const float*)d_in[2]; // [B,R]
    const float* W    = (const float*)d_in[3]; // [R,F]
    const float* bmap = (const float*)d_in[4]; // [F]

    float* out = (float*)d_out;                 // [B,F,K] then [B]
    float* pol = out + (size_t)BB * FF * KK;

    scorer_partial_kernel<<<BB, 256>>>(h_t, W);
    score_kernel<<<BB * 8, 256>>>(emb, mask, bmap);
    topk_kernel<<<BB, 1024>>>(emb, out, pol);
}

// round 15
// speedup vs baseline: 1.6388x; 1.0482x over previous
#include <cuda_runtime.h>
#include <math.h>

// Problem constants (from reference)
#define BB 256
#define GG 2048
#define FF 128
#define RR 512
#define KK 128          // top-k == F
#define TILE_ROWS 32
#define TILE_STRIDE 129
#define HBINS 4096
#define KSLICES 16      // split-K slices for scorer (32 rows each)

// Scratch (static device memory — no allocation)
__device__ float g_part[BB * KSLICES * FF]; // split-K partial sums of h@W
__device__ float g_scores[BB * GG];         // scores (incl. mask)

// float -> order-preserving uint (ascending)
__device__ __forceinline__ unsigned int f2u(float f) {
    unsigned int b = __float_as_uint(f);
    return (b & 0x80000000u) ? ~b : (b | 0x80000000u);
}
__device__ __forceinline__ float u2f(unsigned int u) {
    unsigned int b = (u & 0x80000000u) ? (u & 0x7fffffffu) : ~u;
    return __uint_as_float(b);
}

// warp-level inclusive suffix scan (sum of lanes >= lane)
__device__ __forceinline__ int warp_suffix_incl(int v, int lane) {
    #pragma unroll
    for (int off = 1; off < 32; off <<= 1) {
        int t = __shfl_down_sync(0xffffffffu, v, off);
        if (lane + off < 32) v += t;
    }
    return v;
}

// ================= Kernel 1: scorer split-K partials ========================
// grid 1024 = 64 batch-groups x 16 K-slices (32 rows each), 256 threads.
// ~7 CTAs/SM -> latency of L2 W-loads actually hidden.
// g_part[b][ks][f] = sum_{r in slice ks} h_t[b][r] * W[r][f]
__global__ void __launch_bounds__(256)
scorer_partial_kernel(const float* __restrict__ h_t,   // [B,R]
                      const float* __restrict__ W)     // [R,F]
{
    __shared__ float hs[4][32];      // h slice for 4 batches
    __shared__ float part[4][FF];    // sub-slice combine

    const int tid = threadIdx.x;
    const int bg  = blockIdx.x >> 4;       // batch group 0..63
    const int ks  = blockIdx.x & 15;       // K slice 0..15
    const int b0  = bg * 4;
    const int f   = tid & (FF - 1);
    const int sub = tid >> 7;              // 0/1: rows 0..15 / 16..31 of slice

    if (tid < 128) {
        int bidx = tid >> 5, rl = tid & 31;
        hs[bidx][rl] = h_t[(size_t)(b0 + bidx) * RR + ks * 32 + rl];
    }
    __syncthreads();

    const int rl0 = sub * 16;
    float p0 = 0.f, p1 = 0.f, p2 = 0.f, p3 = 0.f;
    #pragma unroll
    for (int r = 0; r < 16; r++) {
        float wv = W[(size_t)(ks * 32 + rl0 + r) * FF + f];
        p0 += hs[0][rl0 + r] * wv;
        p1 += hs[1][rl0 + r] * wv;
        p2 += hs[2][rl0 + r] * wv;
        p3 += hs[3][rl0 + r] * wv;
    }
    if (sub == 1) {
        part[0][f] = p0; part[1][f] = p1; part[2][f] = p2; part[3][f] = p3;
    }
    __syncthreads();
    if (sub == 0) {
        const size_t base = (size_t)ks * FF + f;
        g_part[(size_t)(b0 + 0) * (KSLICES * FF) + base] = p0 + part[0][f];
        g_part[(size_t)(b0 + 1) * (KSLICES * FF) + base] = p1 + part[1][f];
        g_part[(size_t)(b0 + 2) * (KSLICES * FF) + base] = p2 + part[2][f];
        g_part[(size_t)(b0 + 3) * (KSLICES * FF) + base] = p3 + part[3][f];
    }
}

// ================= Kernel 2: scores (inline scorer finish) ==================
// grid 2048 (= 256 b x 8 slabs), 256 threads. Pure streaming after a tiny
// per-CTA scorer finish (sum partials + bias + tanh + normalize).
__global__ void __launch_bounds__(256)
score_kernel(const float* __restrict__ emb,   // [B,G,F]
             const float* __restrict__ mask,  // [B,G]
             const float* __restrict__ bmap)  // [F]
{
    __shared__ float sc[FF];
    __shared__ float nr[4];
    __shared__ float s_inv;

    const int tid  = threadIdx.x;
    const int cta  = blockIdx.x;
    const int b    = cta >> 3;
    const int slab = cta & 7;
    const int lane = tid & 31;

    if (tid < FF) {
        float acc = bmap[tid];
        #pragma unroll
        for (int ks = 0; ks < KSLICES; ks++)
            acc += g_part[(size_t)b * (KSLICES * FF) + ks * FF + tid];
        float t = tanhf(acc);
        sc[tid] = t;
        float sq = t * t;
        #pragma unroll
        for (int o = 16; o; o >>= 1) sq += __shfl_xor_sync(0xffffffffu, sq, o);
        if (lane == 0) nr[tid >> 5] = sq;
    }
    __syncthreads();
    if (tid == 0) s_inv = rsqrtf(nr[0] + nr[1] + nr[2] + nr[3]);
    __syncthreads();
    const float inv = s_inv;

    const size_t emb_base = (size_t)b * GG * FF;
    const int w  = tid >> 5;
    const int q  = lane >> 2;     // row-in-pass 0..7
    const int lq = lane & 3;      // quad lane 0..3

    float4 scv[8];
    #pragma unroll
    for (int i = 0; i < 8; i++) {
        float4 v = *reinterpret_cast<const float4*>(&sc[lq * 4 + i * 16]);
        v.x *= inv; v.y *= inv; v.z *= inv; v.w *= inv;
        scv[i] = v;
    }

    const int g_base = slab * 256 + w * 32;
    #pragma unroll
    for (int p = 0; p < 4; p++) {
        const int g = g_base + p * 8 + q;
        const float4* rp = reinterpret_cast<const float4*>(emb + emb_base + (size_t)g * FF);
        float d = 0.f;
        #pragma unroll
        for (int i = 0; i < 8; i++) {
            float4 e = rp[lq + i * 4];
            d += e.x * scv[i].x + e.y * scv[i].y + e.z * scv[i].z + e.w * scv[i].w;
        }
        d += __shfl_xor_sync(0xffffffffu, d, 1);
        d += __shfl_xor_sync(0xffffffffu, d, 2);
        if (lq == 0)
            g_scores[(size_t)b * GG + g] = d + mask[(size_t)b * GG + g];
    }
}

// ================= Kernel 3: select + sort + epilogue =======================
// grid 256, 1024 threads.
__global__ void __launch_bounds__(1024, 2)
topk_kernel(const float* __restrict__ emb,    // [B,G,F]
            float* __restrict__ out,          // [B,F,K]
            float* __restrict__ pol)          // [B]
{
    __shared__ unsigned long long histspace[HBINS / 2];   // 16 KB (hist / fallback keys)
    __shared__ unsigned long long cand[256];              // 2 KB
    __shared__ float tile[TILE_ROWS * TILE_STRIDE];       // 16.5 KB
    __shared__ float tanhv[KK];
    __shared__ float redf[32];
    __shared__ int wsum[32];
    __shared__ float s_vmax, s_ssum;
    __shared__ int sB, sCntA, sB2, sCandTotal, sCandCnt;

    unsigned int* hist = (unsigned int*)histspace;

    const int tid  = threadIdx.x;
    const int b    = blockIdx.x;
    const int lane = tid & 31;
    const int w    = tid >> 5;
    const size_t emb_base = (size_t)b * GG * FF;

    // ---- load scores ----
    const float* sp = g_scores + (size_t)b * GG;
    float v0 = sp[tid];
    float v1 = sp[tid + 1024];
    unsigned int u0 = f2u(v0), u1 = f2u(v1);

    // ---- block max ----
    {
        float m = fmaxf(v0, v1);
        #pragma unroll
        for (int o = 16; o; o >>= 1) m = fmaxf(m, __shfl_xor_sync(0xffffffffu, m, o));
        if (lane == 0) redf[w] = m;
    }
    __syncthreads();
    if (w == 0) {
        float m = redf[lane];
        #pragma unroll
        for (int o = 16; o; o >>= 1) m = fmaxf(m, __shfl_xor_sync(0xffffffffu, m, o));
        if (lane == 0) s_vmax = m;
    }
    __syncthreads();
    const float vmax = s_vmax;

    // ---- block expsum ----
    {
        float le = __expf(v0 - vmax) + __expf(v1 - vmax);
        #pragma unroll
        for (int o = 16; o; o >>= 1) le += __shfl_xor_sync(0xffffffffu, le, o);
        if (lane == 0) redf[w] = le;
    }
    __syncthreads();
    if (w == 0) {
        float sm = redf[lane];
        #pragma unroll
        for (int o = 16; o; o >>= 1) sm += __shfl_xor_sync(0xffffffffu, sm, o);
        if (lane == 0) s_ssum = sm;
    }

    // ---- level-1 histogram: bins = key >> 20 ----
    hist[tid] = 0; hist[tid + 1024] = 0; hist[tid + 2048] = 0; hist[tid + 3072] = 0;
    __syncthreads();
    atomicAdd(&hist[u0 >> 20], 1u);
    atomicAdd(&hist[u1 >> 20], 1u);
    __syncthreads();

    // hierarchical suffix scan (2 barriers)
    {
        int s = (int)(hist[4*tid] + hist[4*tid+1] + hist[4*tid+2] + hist[4*tid+3]);
        int v = warp_suffix_incl(s, lane);
        if (lane == 0) wsum[w] = v;          // warp total
        __syncthreads();
        if (w == 0) {
            int t  = wsum[lane];
            int ts = warp_suffix_incl(t, lane);
            wsum[lane] = ts - t;             // sum of warps above
        }
        __syncthreads();
        int Sown  = v + wsum[w];
        int Snext = Sown - s;
        if (Sown >= KK && Snext < KK) {
            int c = Snext;
            for (int bin = 4 * tid + 3; bin >= 4 * tid; bin--) {
                int h = (int)hist[bin];
                if (c + h >= KK) { sB = bin; sCntA = c; break; }
                c += h;
            }
        }
    }
    __syncthreads();
    const int B = sB;
    const int cntA = sCntA;
    const int needed = KK - cntA;

    // ---- level-2 histogram among bin-B elements: bins = (key>>8)&0xFFF ----
    hist[tid] = 0; hist[tid + 1024] = 0; hist[tid + 2048] = 0; hist[tid + 3072] = 0;
    if (tid < 256) cand[tid] = 0ull;
    if (tid == 0) sCandCnt = 0;
    __syncthreads();
    if ((int)(u0 >> 20) == B) atomicAdd(&hist[(u0 >> 8) & 0xFFFu], 1u);
    if ((int)(u1 >> 20) == B) atomicAdd(&hist[(u1 >> 8) & 0xFFFu], 1u);
    __syncthreads();
    {
        int s = (int)(hist[4*tid] + hist[4*tid+1] + hist[4*tid+2] + hist[4*tid+3]);
        int v = warp_suffix_incl(s, lane);
        if (lane == 0) wsum[w] = v;
        __syncthreads();
        if (w == 0) {
            int t  = wsum[lane];
            int ts = warp_suffix_incl(t, lane);
            wsum[lane] = ts - t;
        }
        __syncthreads();
        int Sown  = v + wsum[w];
        int Snext = Sown - s;
        if (Sown >= needed && Snext < needed) {
            int c = Snext;
            for (int bin = 4 * tid + 3; bin >= 4 * tid; bin--) {
                int h = (int)hist[bin];
                if (c + h >= needed) {
                    sB2 = bin;
                    sCandTotal = cntA + c + h;
                    break;
                }
                c += h;
            }
        }
    }
    __syncthreads();
    const int B2 = sB2;
    const int candTotal = sCandTotal;
    const unsigned int thrkey = ((unsigned int)B << 20) | ((unsigned int)B2 << 8);

    if (candTotal <= 256) {
        // ---- compact candidates ----
        if (u0 >= thrkey) {
            int p = atomicAdd(&sCandCnt, 1);
            cand[p] = ((unsigned long long)u0 << 32) | (unsigned int)(GG - 1 - tid);
        }
        if (u1 >= thrkey) {
            int p = atomicAdd(&sCandCnt, 1);
            cand[p] = ((unsigned long long)u1 << 32) | (unsigned int)(GG - 1 - (tid + 1024));
        }
        __syncthreads();
        // ---- bitonic sort 256 candidates, descending ----
        for (int k2 = 2; k2 <= 256; k2 <<= 1) {
            for (int j = k2 >> 1; j > 0; j >>= 1) {
                if (tid < 128) {
                    int i   = ((tid & ~(j - 1)) << 1) | (tid & (j - 1));
                    int ixj = i | j;
                    bool up = ((i & k2) == 0);
                    unsigned long long a = cand[i], c = cand[ixj];
                    if (up ? (a < c) : (a > c)) { cand[i] = c; cand[ixj] = a; }
                }
                __syncthreads();
            }
        }
    } else {
        // ---- fallback (massive ties): full bitonic sort of 2048 ----
        unsigned long long* fullkey = histspace;
        fullkey[tid]        = ((unsigned long long)u0 << 32) | (unsigned int)(GG - 1 - tid);
        fullkey[tid + 1024] = ((unsigned long long)u1 << 32) | (unsigned int)(GG - 1 - (tid + 1024));
        __syncthreads();
        for (int k2 = 2; k2 <= GG; k2 <<= 1) {
            for (int j = k2 >> 1; j > 0; j >>= 1) {
                int i   = ((tid & ~(j - 1)) << 1) | (tid & (j - 1));
                int ixj = i | j;
                bool up = ((i & k2) == 0);
                unsigned long long a = fullkey[i], c = fullkey[ixj];
                if (up ? (a < c) : (a > c)) { fullkey[i] = c; fullkey[ixj] = a; }
                __syncthreads();
            }
        }
        if (tid < 128) cand[tid] = fullkey[tid];
        __syncthreads();
    }

    // ---- tanh(topk) + policy score ----
    if (tid < KK) {
        float v = u2f((unsigned int)(cand[tid] >> 32));
        tanhv[tid] = tanhf(v);
        float tp = v;
        #pragma unroll
        for (int o = 16; o; o >>= 1) tp += __shfl_xor_sync(0xffffffffu, tp, o);
        if (lane == 0) redf[w] = tp;   // warps 0..3
    }
    __syncthreads();
    if (tid == 0) {
        float topsum = redf[0] + redf[1] + redf[2] + redf[3];
        pol[b] = topsum * (1.0f / KK) - vmax - __logf(s_ssum);
    }

    // ---- chunked gather (32 rows) + transposed, scaled write ----
    #pragma unroll 1
    for (int c = 0; c < KK / TILE_ROWS; c++) {
        {
            const int k   = c * TILE_ROWS + w;
            const int row = GG - 1 - (int)(unsigned int)(cand[k] & 0xffffffffu);
            float4 e = *reinterpret_cast<const float4*>(
                emb + emb_base + (size_t)row * FF + lane * 4);
            // scalar stores: &tile[w*129 + lane*4] not 16B-aligned for odd w
            float* tp2 = &tile[w * TILE_STRIDE + lane * 4];
            tp2[0] = e.x; tp2[1] = e.y; tp2[2] = e.z; tp2[3] = e.w;
        }
        __syncthreads();
        {
            const int kl = tid & 31;
            const int f0 = tid >> 5;     // 0..31
            const float tv = tanhv[c * TILE_ROWS + kl];
            float* ob = out + (size_t)b * FF * KK + c * TILE_ROWS;
            #pragma unroll
            for (int f = f0; f < FF; f += 32)
                ob[(size_t)f * KK + kl] = tile[kl * TILE_STRIDE + f] * tv;
        }
        __syncthreads();
    }
}

extern "C" void kernel_launch(void* const* d_in, const int* in_sizes, int n_in,
                              void* d_out, int out_size) {
    const float* emb  = (const float*)d_in[0]; // node_embs [B,G,F]
    const float* mask = (const float*)d_in[1]; // [B,G]
    const float* h_t  = (const float*)d_in[2]; // [B,R]
    const float* W    = (const float*)d_in[3]; // [R,F]
    const float* bmap = (const float*)d_in[4]; // [F]

    float* out = (float*)d_out;                 // [B,F,K] then [B]
    float* pol = out + (size_t)BB * FF * KK;

    scorer_partial_kernel<<<64 * KSLICES, 256>>>(h_t, W);
    score_kernel<<<BB * 8, 256>>>(emb, mask, bmap);
    topk_kernel<<<BB, 1024>>>(emb, out, pol);
}